// round 10
// baseline (speedup 1.0000x reference)
#include <cuda_runtime.h>
#include <cuda_fp16.h>
#include <cuda_bf16.h>
#include <cstdint>

// Problem constants
#define NB   128          // batch
#define NT   64           // max timesteps
#define NE   512          // embedding dim
#define NH   1024         // hidden dim
#define N3H  3072         // 3*H (gate order r,z,n)
#define NBT  (NB*NT)      // 8192 rows for xgates GEMM

// k_recur geometry: CTA owns 32 units x 32 batch rows; 8 compute + 1 loader warp
#define UCNT   32                 // hidden units per CTA
#define BROWS  32                 // batch rows per CTA
#define SWROWS 96                 // 3 gates * 32 units
#define SWW    520                // w_hh row stride: 512 words + 8 pad (LDS.64 ok)
#define SHW    68                 // h stage row stride: 64 words (128 fp16) + 4 pad
#define NSTG   3                  // smem ring depth
#define STGW   (BROWS * SHW)      // words per stage (2176)

// Scratch (device globals; no runtime allocation allowed)
__device__ float g_xg[(size_t)NT * NB * N3H];              // [t][b][3H]
__device__ __align__(16) __half g_h16[2][NB * NH];         // fp16 h exchange (L2)
__device__ __align__(16) __half g_a16[(size_t)NBT * NE];   // gathered emb, fp16
__device__ __align__(16) __half g_w16[(size_t)N3H * NE];   // w_ih, fp16
__device__ float g_final[NB * NH];                         // h at t == len-1
__device__ unsigned g_qf[4][32][8];                        // [bq][ug] flags, 32B spaced

// ---------------------------------------------------------------------------
// helpers
// ---------------------------------------------------------------------------
__device__ __forceinline__ void mma_f16(float c[4], const uint32_t a[4],
                                        uint32_t b0, uint32_t b1) {
    asm volatile(
        "mma.sync.aligned.m16n8k16.row.col.f32.f16.f16.f32 "
        "{%0,%1,%2,%3}, {%4,%5,%6,%7}, {%8,%9}, {%0,%1,%2,%3};"
        : "+f"(c[0]), "+f"(c[1]), "+f"(c[2]), "+f"(c[3])
        : "r"(a[0]), "r"(a[1]), "r"(a[2]), "r"(a[3]), "r"(b0), "r"(b1));
}

__device__ __forceinline__ void ldsm_x4(uint32_t a[4], uint32_t saddr) {
    asm volatile(
        "ldmatrix.sync.aligned.m8n8.x4.shared.b16 {%0,%1,%2,%3}, [%4];"
        : "=r"(a[0]), "=r"(a[1]), "=r"(a[2]), "=r"(a[3]) : "r"(saddr));
}

__device__ __forceinline__ void cp_async16(uint32_t saddr, const void* gaddr) {
    asm volatile("cp.async.cg.shared.global [%0], [%1], 16;"
                 :: "r"(saddr), "l"(gaddr));
}
__device__ __forceinline__ void cp_commit() {
    asm volatile("cp.async.commit_group;");
}
template <int N>
__device__ __forceinline__ void cp_wait() {
    asm volatile("cp.async.wait_group %0;" :: "n"(N));
}

__device__ __forceinline__ unsigned ld_acq(const unsigned* p) {
    unsigned v;
    asm volatile("ld.acquire.gpu.global.u32 %0, [%1];" : "=r"(v) : "l"(p));
    return v;
}
__device__ __forceinline__ void st_rel(unsigned* p, unsigned v) {
    asm volatile("st.release.gpu.global.u32 [%0], %1;" :: "l"(p), "r"(v));
}

__device__ __forceinline__ uint32_t packh2(float x, float y) {
    __half2 p = __floats2half2_rn(x, y);
    return *reinterpret_cast<uint32_t*>(&p);
}

// mbarrier primitives
__device__ __forceinline__ void mbar_init(uint32_t mbar, uint32_t cnt) {
    asm volatile("mbarrier.init.shared.b64 [%0], %1;" :: "r"(mbar), "r"(cnt)
                 : "memory");
}
__device__ __forceinline__ void mbar_inval(uint32_t mbar) {
    asm volatile("mbarrier.inval.shared.b64 [%0];" :: "r"(mbar) : "memory");
}
__device__ __forceinline__ void mbar_arrive(uint32_t mbar) {
    asm volatile("mbarrier.arrive.shared.b64 _, [%0];" :: "r"(mbar) : "memory");
}
__device__ __forceinline__ void mbar_wait(uint32_t mbar, uint32_t parity) {
    uint32_t done;
    do {
        asm volatile(
            "{\n\t.reg .pred p;\n\t"
            "mbarrier.try_wait.parity.shared.b64 p, [%1], %2;\n\t"
            "selp.b32 %0, 1, 0, p;\n\t}"
            : "=r"(done) : "r"(mbar), "r"(parity) : "memory");
    } while (!done);
}

// ---------------------------------------------------------------------------
// k_init: zero h16[0] and flags
// ---------------------------------------------------------------------------
__global__ void k_init() {
    int i = blockIdx.x * blockDim.x + threadIdx.x;
    if (i < NB * NH) g_h16[0][i] = __float2half(0.0f);
    if (i < 4 * 32 * 8) ((unsigned*)g_qf)[i] = 0u;
}

// ---------------------------------------------------------------------------
// k_cvt: gather emb rows per (b,t) token and convert to fp16; convert w_ih.
// ---------------------------------------------------------------------------
__global__ void __launch_bounds__(128)
k_cvt(const int* __restrict__ sent, const float* __restrict__ emb,
      const float* __restrict__ w_ih) {
    const int row = blockIdx.x;
    const int tid = threadIdx.x;
    const float* src;
    __half* dst;
    if (row < NBT) {
        src = emb + (size_t)sent[row] * NE;
        dst = g_a16 + (size_t)row * NE;
    } else {
        src = w_ih + (size_t)(row - NBT) * NE;
        dst = g_w16 + (size_t)(row - NBT) * NE;
    }
    const float4 v = reinterpret_cast<const float4*>(src)[tid];
    uint2 u;
    u.x = packh2(v.x, v.y);
    u.y = packh2(v.z, v.w);
    reinterpret_cast<uint2*>(dst)[tid] = u;
}

// ---------------------------------------------------------------------------
// k_xgates: fp16 GEMM. xg[t][b][n] = a16[m] . w16[n] + b_ih[n]  (unchanged)
// ---------------------------------------------------------------------------
__global__ void __launch_bounds__(256, 2)
k_xgates(const float* __restrict__ b_ih) {
    extern __shared__ uint32_t xsm[];
    uint32_t* sA = xsm;                    // [2][128][36]
    uint32_t* sB = xsm + 2 * 128 * 36;     // [2][128][36]

    const int tid  = threadIdx.x;
    const int wid  = tid >> 5;
    const int lane = tid & 31;
    const int g    = lane >> 2;
    const int t4   = lane & 3;

    const int m0 = blockIdx.y * 128;
    const int n0 = blockIdx.x * 128;
    const int wm = (wid & 3) * 32;
    const int wn = (wid >> 2) * 64;

    int ldrow[4], ldc16[4];
#pragma unroll
    for (int p = 0; p < 4; p++) {
        int idx = tid + p * 256;
        ldrow[p] = idx >> 3;
        ldc16[p] = idx & 7;
    }

    float c[2][8][4];
#pragma unroll
    for (int mf = 0; mf < 2; mf++)
#pragma unroll
        for (int nt = 0; nt < 8; nt++)
#pragma unroll
            for (int e = 0; e < 4; e++) c[mf][nt][e] = 0.0f;

#pragma unroll
    for (int p = 0; p < 4; p++) {
        uint32_t sa = (uint32_t)__cvta_generic_to_shared(
            sA + ldrow[p] * 36 + ldc16[p] * 4);
        cp_async16(sa, g_a16 + (size_t)(m0 + ldrow[p]) * NE + ldc16[p] * 8);
        uint32_t sb = (uint32_t)__cvta_generic_to_shared(
            sB + ldrow[p] * 36 + ldc16[p] * 4);
        cp_async16(sb, g_w16 + (size_t)(n0 + ldrow[p]) * NE + ldc16[p] * 8);
    }
    cp_commit();

    for (int kt = 0; kt < 8; kt++) {
        const int cur = kt & 1;
        if (kt + 1 < 8) {
            const int nxt = cur ^ 1;
            const int kk = (kt + 1) * 64;
#pragma unroll
            for (int p = 0; p < 4; p++) {
                uint32_t sa = (uint32_t)__cvta_generic_to_shared(
                    sA + nxt * 128 * 36 + ldrow[p] * 36 + ldc16[p] * 4);
                cp_async16(sa, g_a16 + (size_t)(m0 + ldrow[p]) * NE + kk + ldc16[p] * 8);
                uint32_t sb = (uint32_t)__cvta_generic_to_shared(
                    sB + nxt * 128 * 36 + ldrow[p] * 36 + ldc16[p] * 4);
                cp_async16(sb, g_w16 + (size_t)(n0 + ldrow[p]) * NE + kk + ldc16[p] * 8);
            }
        }
        cp_commit();
        cp_wait<1>();
        __syncthreads();

        const uint32_t* A = sA + cur * 128 * 36;
        const uint32_t* B = sB + cur * 128 * 36;
#pragma unroll
        for (int kb = 0; kb < 32; kb += 8) {
            uint32_t a[2][4];
#pragma unroll
            for (int mf = 0; mf < 2; mf++) {
                int r = wm + mf * 16 + g;
                a[mf][0] = A[r * 36 + kb + t4];
                a[mf][1] = A[(r + 8) * 36 + kb + t4];
                a[mf][2] = A[r * 36 + kb + t4 + 4];
                a[mf][3] = A[(r + 8) * 36 + kb + t4 + 4];
            }
#pragma unroll
            for (int nt = 0; nt < 8; nt++) {
                uint32_t b0 = B[(wn + nt * 8 + g) * 36 + kb + t4];
                uint32_t b1 = B[(wn + nt * 8 + g) * 36 + kb + t4 + 4];
                mma_f16(c[0][nt], a[0], b0, b1);
                mma_f16(c[1][nt], a[1], b0, b1);
            }
        }
        __syncthreads();
    }

#pragma unroll
    for (int mf = 0; mf < 2; mf++) {
#pragma unroll
        for (int nt = 0; nt < 8; nt++) {
#pragma unroll
            for (int half = 0; half < 2; half++) {
                int m = m0 + wm + mf * 16 + g + half * 8;
                int b = m >> 6;
                int tt = m & 63;
                int n = n0 + wn + nt * 8 + (t4 << 1);
                float2 out;
                out.x = c[mf][nt][half * 2 + 0] + __ldg(b_ih + n);
                out.y = c[mf][nt][half * 2 + 1] + __ldg(b_ih + n + 1);
                *reinterpret_cast<float2*>(
                    &g_xg[((size_t)tt * NB + b) * N3H + n]) = out;
            }
        }
    }
}

// ---------------------------------------------------------------------------
// k_recur: PERSISTENT GRU recurrence, warp-specialized producer/consumer.
// 288 threads: warps 0-7 compute (R7 layout: warp = bh x uh, m16 x n24, full
// K), warp 8 = loader (flag polling + all h cp.asyncs). Per-stage smem
// mbarriers (full cnt=32, empty cnt=8) replace all in-loop __syncthreads.
// Loader runs up to 2 stages ahead, crossing step boundaries; stage s of
// step t only needs producer flags ug=4s..4s+3 >= t.
// Dynamic smem = 96*520 + 3*2176 + 16 words = 225,856 B.
// ---------------------------------------------------------------------------
__global__ void __launch_bounds__(288)
k_recur(const int* __restrict__ slen, const float* __restrict__ w_hh,
        const float* __restrict__ b_hh) {
    extern __shared__ uint32_t sm[];
    uint32_t* sW = sm;                    // [96][SWW] fragment-paired
    uint32_t* sH = sm + SWROWS * SWW;     // [NSTG][32][SHW]
    const uint32_t mb = (uint32_t)__cvta_generic_to_shared(
        sm + SWROWS * SWW + NSTG * STGW); // full[i]@mb+8i, empty[i]@mb+24+8i
    const uint32_t sh_base = (uint32_t)__cvta_generic_to_shared(sH);

    const int tid  = threadIdx.x;
    const int wid  = tid >> 5;
    const int lane = tid & 31;
    const int g    = lane >> 2;
    const int t4   = lane & 3;

    const int ug = blockIdx.x >> 2;       // unit group 0..31
    const int bq = blockIdx.x & 3;        // batch quarter 0..3
    const int j0 = ug * UCNT;
    const int b0 = bq * BROWS;

    // ---- convert w_hh rows to fragment-paired fp16 smem layout (once) ----
    for (int i = tid; i < SWROWS * 64; i += 288) {
        int r  = i >> 6;
        int kc = i & 63;
        int grow = (r >> 5) * NH + j0 + (r & 31);
        const float4* src = reinterpret_cast<const float4*>(
            w_hh + (size_t)grow * NH + kc * 16);
        float4 v0 = src[0], v1 = src[1], v2 = src[2], v3 = src[3];
        uint32_t w0 = packh2(v0.x, v0.y), w1 = packh2(v0.z, v0.w);
        uint32_t w2 = packh2(v1.x, v1.y), w3 = packh2(v1.z, v1.w);
        uint32_t w4 = packh2(v2.x, v2.y), w5 = packh2(v2.z, v2.w);
        uint32_t w6 = packh2(v3.x, v3.y), w7 = packh2(v3.z, v3.w);
        uint32_t* d = sW + r * SWW + kc * 8;
        d[0] = w0; d[1] = w4;
        d[2] = w1; d[3] = w5;
        d[4] = w2; d[5] = w6;
        d[6] = w3; d[7] = w7;
    }

    if (tid == 0) {
#pragma unroll
        for (int i = 0; i < NSTG; i++) {
            mbar_init(mb + i * 8, 32);        // full: 32 loader lanes
            mbar_init(mb + 24 + i * 8, 8);    // empty: 8 compute warps
        }
    }
    __syncthreads();   // sW + mbarriers ready (all 288 threads)

    if (wid < 8) {
        // =================== COMPUTE WARPS ===================
        const int bh = wid & 1;
        const int uh = wid >> 1;

        const int r0c = bh * 16 + g;
        const int r0g = b0 + r0c;
        const int r1g = r0g + 8;
        const int ja  = j0 + uh * 8 + (t4 << 1);
        const int len0 = slen[r0g] - 1;
        const int len1 = slen[r1g] - 1;
        const float bra = b_hh[ja],          brb = b_hh[ja + 1];
        const float bza = b_hh[NH + ja],     bzb = b_hh[NH + ja + 1];
        const float bna = b_hh[2 * NH + ja], bnb = b_hh[2 * NH + ja + 1];

        const int wr0 = (0 * UCNT + uh * 8 + g) * SWW;
        const int wr1 = (1 * UCNT + uh * 8 + g) * SWW;
        const int wr2 = (2 * UCNT + uh * 8 + g) * SWW;

        const int lm_row = bh * 16 + (lane & 7) + ((lane >> 3) & 1) * 8;
        const int lm_wrd = ((lane >> 4) & 1) * 4;
        const uint32_t lm_off = (uint32_t)((lm_row * SHW + lm_wrd) * 4);

        float2 hprev0 = make_float2(0.0f, 0.0f);
        float2 hprev1 = make_float2(0.0f, 0.0f);

        int slot = 0;
        uint32_t par = 0;

        for (int t = 0; t < NT; t++) {
            // prefetch epilogue x-gate operands
            const float* xg0 = g_xg + ((size_t)t * NB + r0g) * N3H + ja;
            const float* xg1 = g_xg + ((size_t)t * NB + r1g) * N3H + ja;
            float2 xr0 = __ldg((const float2*)(xg0));
            float2 xz0 = __ldg((const float2*)(xg0 + NH));
            float2 xn0 = __ldg((const float2*)(xg0 + 2 * NH));
            float2 xr1 = __ldg((const float2*)(xg1));
            float2 xz1 = __ldg((const float2*)(xg1 + NH));
            float2 xn1 = __ldg((const float2*)(xg1 + 2 * NH));

            float c[3][4];
#pragma unroll
            for (int nt = 0; nt < 3; nt++)
#pragma unroll
                for (int e = 0; e < 4; e++) c[nt][e] = 0.0f;

            for (int s = 0; s < 8; s++) {
                mbar_wait(mb + slot * 8, par);
                const uint32_t a_base = sh_base + (uint32_t)(slot * STGW * 4) + lm_off;
#pragma unroll
                for (int kc = 0; kc < 8; kc++) {
                    uint32_t a[4];
                    ldsm_x4(a, a_base + kc * 32);
                    const int wo = (s * 8 + kc) * 8 + t4 * 2;
                    uint2 wv0 = *reinterpret_cast<const uint2*>(sW + wr0 + wo);
                    uint2 wv1 = *reinterpret_cast<const uint2*>(sW + wr1 + wo);
                    uint2 wv2 = *reinterpret_cast<const uint2*>(sW + wr2 + wo);
                    mma_f16(c[0], a, wv0.x, wv0.y);
                    mma_f16(c[1], a, wv1.x, wv1.y);
                    mma_f16(c[2], a, wv2.x, wv2.y);
                }
                if (lane == 0) mbar_arrive(mb + 24 + slot * 8);
                if (++slot == NSTG) { slot = 0; par ^= 1; }
            }

            // fused GRU gate epilogue
            __half* __restrict__ h16_out = g_h16[(t & 1) ^ 1];
            float hnew[4];
#pragma unroll
            for (int e = 0; e < 4; e++) {
                const int half = e >> 1;
                const int sub  = e & 1;
                float xrv = half ? (sub ? xr1.y : xr1.x) : (sub ? xr0.y : xr0.x);
                float xzv = half ? (sub ? xz1.y : xz1.x) : (sub ? xz0.y : xz0.x);
                float xnv = half ? (sub ? xn1.y : xn1.x) : (sub ? xn0.y : xn0.x);
                float hov = half ? (sub ? hprev1.y : hprev1.x)
                                 : (sub ? hprev0.y : hprev0.x);
                float hr = c[0][e] + (sub ? brb : bra);
                float hz = c[1][e] + (sub ? bzb : bza);
                float hh = c[2][e] + (sub ? bnb : bna);
                float rr = 1.0f / (1.0f + expf(-(xrv + hr)));
                float zz = 1.0f / (1.0f + expf(-(xzv + hz)));
                float nn = tanhf(xnv + rr * hh);
                hnew[e] = (1.0f - zz) * nn + zz * hov;
            }
            hprev0 = make_float2(hnew[0], hnew[1]);
            hprev1 = make_float2(hnew[2], hnew[3]);
            __stcg((__half2*)(h16_out + (size_t)r0g * NH + ja),
                   __floats2half2_rn(hnew[0], hnew[1]));
            __stcg((__half2*)(h16_out + (size_t)r1g * NH + ja),
                   __floats2half2_rn(hnew[2], hnew[3]));
            if (len0 == t)
                *(float2*)(g_final + (size_t)r0g * NH + ja) = make_float2(hnew[0], hnew[1]);
            if (len1 == t)
                *(float2*)(g_final + (size_t)r1g * NH + ja) = make_float2(hnew[2], hnew[3]);

            // compute-only barrier, then publish
            asm volatile("bar.sync 1, 256;" ::: "memory");
            if (tid == 0) {
                asm volatile("fence.acq_rel.gpu;" ::: "memory");
                st_rel(&g_qf[bq][ug][0], (unsigned)(t + 1));
            }
        }
    } else {
        // =================== LOADER WARP ===================
        const int l = lane;
        int slot = 0;
        uint32_t par = 1;          // producer-flipped phase: first waits pass
        int arrived = -1;          // highest stage whose full-barrier has arrived

        for (int u = 0; u < NT * 8; u++) {
            const int t = u >> 3;
            const int s = u & 7;

            // retire stage u-2 (keeps 2-deep lookahead)
            if (u - 2 > arrived && u >= 2) {
                cp_wait<1>();
                mbar_arrive(mb + ((u - 2) % NSTG) * 8);
                arrived = u - 2;
            }

            // ring slot must be free
            mbar_wait(mb + 24 + slot * 8, par);

            // producer flags for this stage's k-range (ug 4s..4s+3)
            unsigned rdy = 1;
            if (l < 4) rdy = (ld_acq(&g_qf[bq][4 * s + l][0]) >= (unsigned)t);
            unsigned mask = __ballot_sync(0xffffffffu, rdy);
            if (mask != 0xffffffffu) {
                // will block: retire everything outstanding so compute can drain
                if (u - 1 > arrived && u >= 1) {
                    cp_wait<0>();
                    mbar_arrive(mb + ((u - 1) % NSTG) * 8);
                    arrived = u - 1;
                }
                if (l < 4) {
                    while (ld_acq(&g_qf[bq][4 * s + l][0]) < (unsigned)t) { }
                }
                __syncwarp();
            }

            // issue the 8 KB stage: 512 chunks of 16B, 16 per lane
            const __half* __restrict__ hin = g_h16[t & 1];
            const uint32_t dst = sh_base + (uint32_t)(slot * STGW * 4);
#pragma unroll
            for (int i = 0; i < 16; i++) {
                const int ch  = l + 32 * i;
                const int row = ch >> 4;
                const int col = ch & 15;
                cp_async16(dst + (uint32_t)((row * SHW + col * 4) * 4),
                           hin + (size_t)(b0 + row) * NH + s * 128 + col * 8);
            }
            cp_commit();

            if (++slot == NSTG) { slot = 0; par ^= 1; }
        }
        // drain
        if (NT * 8 - 2 > arrived) {
            cp_wait<1>();
            mbar_arrive(mb + ((NT * 8 - 2) % NSTG) * 8);
        }
        cp_wait<0>();
        mbar_arrive(mb + ((NT * 8 - 1) % NSTG) * 8);
    }

    // cleanup: invalidate mbarriers so graph replay re-inits cleanly
    __syncthreads();
    if (tid == 0) {
#pragma unroll
        for (int i = 0; i < NSTG; i++) {
            mbar_inval(mb + i * 8);
            mbar_inval(mb + 24 + i * 8);
        }
    }
}

// ---------------------------------------------------------------------------
// k_norm: L2-normalize each final row, write output
// ---------------------------------------------------------------------------
__global__ void __launch_bounds__(256)
k_norm(float* __restrict__ out) {
    const int b = blockIdx.x;
    const int tid = threadIdx.x;
    float s = 0.0f;
    for (int j = tid; j < NH; j += 256) {
        float v = g_final[(size_t)b * NH + j];
        s += v * v;
    }
#pragma unroll
    for (int o = 16; o; o >>= 1) s += __shfl_xor_sync(0xFFFFFFFFu, s, o);
    __shared__ float ws[8];
    __shared__ float s_norm;
    if ((tid & 31) == 0) ws[tid >> 5] = s;
    __syncthreads();
    if (tid == 0) {
        float x = 0.0f;
#pragma unroll
        for (int i = 0; i < 8; i++) x += ws[i];
        s_norm = sqrtf(x);
    }
    __syncthreads();
    float inv = 1.0f / s_norm;
    for (int j = tid; j < NH; j += 256)
        out[(size_t)b * NH + j] = g_final[(size_t)b * NH + j] * inv;
}

// ---------------------------------------------------------------------------
// entry point
// ---------------------------------------------------------------------------
extern "C" void kernel_launch(void* const* d_in, const int* in_sizes, int n_in,
                              void* d_out, int out_size) {
    const int*   sent  = (const int*)d_in[0];
    const int*   slen  = (const int*)d_in[1];
    const float* emb   = (const float*)d_in[2];
    const float* w_ih  = (const float*)d_in[3];
    const float* w_hh  = (const float*)d_in[4];
    const float* b_ih  = (const float*)d_in[5];
    const float* b_hh  = (const float*)d_in[6];

    const int smem_xg    = 2 * 2 * 128 * 36 * 4;                        // 73,728 B
    const int smem_recur = (SWROWS * SWW + NSTG * STGW + 16) * 4;       // 225,856 B
    cudaFuncSetAttribute(k_xgates, cudaFuncAttributeMaxDynamicSharedMemorySize,
                         smem_xg);
    cudaFuncSetAttribute(k_recur, cudaFuncAttributeMaxDynamicSharedMemorySize,
                         smem_recur);

    k_init<<<512, 256>>>();
    k_cvt<<<NBT + N3H, 128>>>(sent, emb, w_ih);
    k_xgates<<<dim3(N3H / 128, NBT / 128), 256, smem_xg>>>(b_ih);
    k_recur<<<128, 288, smem_recur>>>(slen, w_hh, b_hh);
    k_norm<<<NB, 256>>>((float*)d_out);
}